// round 15
// baseline (speedup 1.0000x reference)
#include <cuda_runtime.h>

// Problem constants
static constexpr int NB   = 4096;
static constexpr int CN   = 62;
static constexpr int FIN  = 256;
static constexpr int HID  = 64;
static constexpr int TOPK = 10;
static constexpr int NT   = 768;   // 24 warps

// SMEM strides (floats)
static constexpr int XS_LD = 260;
static constexpr int HB_LD = 68;

// SMEM layout (floats)
static constexpr int XS_OFF   = 0;                  // 16640 (x; ADJ overlays later)
static constexpr int ADJ_OFF  = 0;
static constexpr int WB_OFF   = 16640;              // 21760: ph1 = 5 slots; ph5 = 2x2-slot double buffer
static constexpr int WSLOT    = 4352;
static constexpr int MASK_OFF = WB_OFF + 21760;     // 38400
static constexpr int HH_OFF   = MASK_OFF + 4352;    // 42752 (xa then h)
static constexpr int A_OFF    = HH_OFF + 4352;      // 47104
static constexpr int B_OFF    = A_OFF + 4352;       // 51456
static constexpr int TV_OFF   = B_OFF + 4352;       // 55808
static constexpr int TI_OFF   = TV_OFF + 620;       // 56428
static constexpr int SMEM_FLOATS = TI_OFF + 620;    // 57048 fl = 228192 B

// Pre-transposed tf32 weights in device global
static constexpr int W1SLOT_F  = 16384;
static constexpr int MIDREL_F  = 5 * W1SLOT_F;          // 81920
static constexpr int MIDROOT_F = MIDREL_F + 6 * 4096;   // 106496
static constexpr int WT_FLOATS = MIDROOT_F + 6 * 4096;  // 131072
__device__ float g_wT[WT_FLOATS];

typedef unsigned long long ull;
typedef unsigned int uint32;

__device__ __forceinline__ ull ffma2(ull a, ull b, ull c) {
    ull d; asm("fma.rn.f32x2 %0, %1, %2, %3;" : "=l"(d) : "l"(a), "l"(b), "l"(c)); return d;
}
__device__ __forceinline__ ull pack2(float x) {
    ull r; asm("mov.b64 %0, {%1, %1};" : "=l"(r) : "f"(x)); return r;
}
__device__ __forceinline__ float2 unpack2(ull v) {
    float2 r; asm("mov.b64 {%0, %1}, %2;" : "=f"(r.x), "=f"(r.y) : "l"(v)); return r;
}
__device__ __forceinline__ uint32 cvt_tf32(float x) {
    uint32 r; asm("cvt.rna.tf32.f32 %0, %1;" : "=r"(r) : "f"(x)); return r;
}
__device__ __forceinline__ void mma_tf32(float* d, uint32 a0, uint32 a1, uint32 a2, uint32 a3,
                                         uint32 b0, uint32 b1) {
    asm volatile(
        "mma.sync.aligned.m16n8k8.row.col.f32.tf32.tf32.f32 "
        "{%0,%1,%2,%3}, {%4,%5,%6,%7}, {%8,%9}, {%0,%1,%2,%3};"
        : "+f"(d[0]), "+f"(d[1]), "+f"(d[2]), "+f"(d[3])
        : "r"(a0), "r"(a1), "r"(a2), "r"(a3), "r"(b0), "r"(b1));
}

// ---- prep kernel: transpose + tf32-convert all weights once per launch ----
__global__ void prep_weights(
    const float* __restrict__ gate_w,  const float* __restrict__ bnlin_w,
    const float* __restrict__ rel_w1,  const float* __restrict__ root_w1,
    const float* __restrict__ rel_w_mid, const float* __restrict__ root_w_mid)
{
    int i = blockIdx.x * blockDim.x + threadIdx.x;
    if (i < 16384) {
        int n = i >> 8, k = i & 255;
        int src = k * 64 + n;
        int dst = n * 256 + k;
        g_wT[0 * W1SLOT_F + dst] = __uint_as_float(cvt_tf32(__ldg(&gate_w[src])));
        g_wT[1 * W1SLOT_F + dst] = __uint_as_float(cvt_tf32(__ldg(&rel_w1[src])));
        g_wT[2 * W1SLOT_F + dst] = __uint_as_float(cvt_tf32(__ldg(&root_w1[src])));
        float bn = __ldg(&bnlin_w[src]);
        uint32 hi = cvt_tf32(bn);
        g_wT[3 * W1SLOT_F + dst] = __uint_as_float(hi);
        g_wT[4 * W1SLOT_F + dst] = __uint_as_float(cvt_tf32(bn - __uint_as_float(hi)));
    }
    if (i < 24576) {
        int L = i >> 12, idx = i & 4095;
        int n = idx >> 6, k = idx & 63;
        int src = L * 4096 + k * 64 + n;
        int dst = L * 4096 + n * 64 + k;
        g_wT[MIDREL_F + dst]  = __uint_as_float(cvt_tf32(__ldg(&rel_w_mid[src])));
        g_wT[MIDROOT_F + dst] = __uint_as_float(cvt_tf32(__ldg(&root_w_mid[src])));
    }
}

__global__ __launch_bounds__(NT, 1) void residual_graph_kernel(
    const float* __restrict__ x,
    const float* __restrict__ gate_b,
    const float* __restrict__ bnlin_b,
    const float* __restrict__ rel_b1,
    const float* __restrict__ rel_b_mid,
    float* __restrict__ out)
{
    extern __shared__ float sm[];
    const int b    = blockIdx.x;
    const int tid  = threadIdx.x;
    const int lane = tid & 31;
    const int wid  = tid >> 5;

    const float4* wT4 = reinterpret_cast<const float4*>(g_wT);
    float4* wb4 = reinterpret_cast<float4*>(sm + WB_OFF);

    // ---------------- Phase 0: load x tile ----------------
    {
        const float4* xg  = reinterpret_cast<const float4*>(x + (size_t)b * (CN * FIN));
        float4*       xs4 = reinterpret_cast<float4*>(sm + XS_OFF);
        for (int i = tid; i < CN * 64; i += NT) {
            int r = i >> 6, q = i & 63;
            xs4[r * (XS_LD / 4) + q] = xg[i];
        }
        float4 z = make_float4(0.f, 0.f, 0.f, 0.f);
        if (tid < 2 * 64) {
            int r = 62 + (tid >> 6), q = tid & 63;
            xs4[r * (XS_LD / 4) + q] = z;
        }
    }
    __syncthreads();

    // ---- Phase 1: four [62,256]x[256,64] GEMMs, 24-warp balanced ----------
    // Warps 0-15: bnlin N16 unit (3-chain) + gate N16 unit (shared x_hi frags).
    // Warps 16-23: 4 units of rel/root (same nq -> B frags shared across ms).
    {
        const int lr = lane >> 2, lk = lane & 3;
        float acc[32];
        #pragma unroll
        for (int i = 0; i < 32; ++i) acc[i] = 0.f;

        for (int ch = 0; ch < 4; ++ch) {
            // stage 5 pre-transposed tf32 weight chunks, float4, conflict-free
            for (int g = tid; g < 1024; g += NT) {
                int n = g >> 4, kq = g & 15;
                int srcb = n * 64 + ch * 16 + kq;
                int dst  = n * 17 + kq;
                wb4[0 * 1088 + dst] = wT4[0 * 4096 + srcb];
                wb4[1 * 1088 + dst] = wT4[1 * 4096 + srcb];
                wb4[2 * 1088 + dst] = wT4[2 * 4096 + srcb];
                wb4[3 * 1088 + dst] = wT4[3 * 4096 + srcb];
                wb4[4 * 1088 + dst] = wT4[4 * 4096 + srcb];
            }
            __syncthreads();

            if (wid < 16) {
                const int ms = wid & 3, nq = wid >> 2;
                const int r0 = ms * 16 + lr;
                const float* wg  = sm + WB_OFF + 0 * WSLOT;
                const float* whi = sm + WB_OFF + 3 * WSLOT;
                const float* wlo = sm + WB_OFF + 4 * WSLOT;
                #pragma unroll
                for (int step = 0; step < 8; ++step) {
                    int kc = ch * 64 + step * 8 + lk;
                    float x0 = sm[XS_OFF + r0 * XS_LD + kc];
                    float x1 = sm[XS_OFF + (r0 + 8) * XS_LD + kc];
                    float x2 = sm[XS_OFF + r0 * XS_LD + kc + 4];
                    float x3 = sm[XS_OFF + (r0 + 8) * XS_LD + kc + 4];
                    uint32 h0 = cvt_tf32(x0), h1 = cvt_tf32(x1), h2 = cvt_tf32(x2), h3 = cvt_tf32(x3);
                    uint32 l0 = cvt_tf32(x0 - __uint_as_float(h0));
                    uint32 l1 = cvt_tf32(x1 - __uint_as_float(h1));
                    uint32 l2 = cvt_tf32(x2 - __uint_as_float(h2));
                    uint32 l3 = cvt_tf32(x3 - __uint_as_float(h3));
                    int kw = step * 8 + lk;
                    #pragma unroll
                    for (int t = 0; t < 2; ++t) {
                        int n = nq * 16 + t * 8 + lr;
                        uint32 bh0 = __float_as_uint(whi[n * HB_LD + kw]);
                        uint32 bh1 = __float_as_uint(whi[n * HB_LD + kw + 4]);
                        uint32 bl0 = __float_as_uint(wlo[n * HB_LD + kw]);
                        uint32 bl1 = __float_as_uint(wlo[n * HB_LD + kw + 4]);
                        mma_tf32(&acc[t * 4], h0, h1, h2, h3, bh0, bh1);
                        mma_tf32(&acc[t * 4], h0, h1, h2, h3, bl0, bl1);
                        mma_tf32(&acc[t * 4], l0, l1, l2, l3, bh0, bh1);
                        uint32 g0 = __float_as_uint(wg[n * HB_LD + kw]);
                        uint32 g1 = __float_as_uint(wg[n * HB_LD + kw + 4]);
                        mma_tf32(&acc[8 + t * 4], h0, h1, h2, h3, g0, g1);
                    }
                }
            } else {
                const int w2 = wid - 16;
                const int matU = w2 >> 2, nq = w2 & 3;   // matU 0 rel, 1 root
                const float* wt = sm + WB_OFF + (1 + matU) * WSLOT;
                #pragma unroll
                for (int step = 0; step < 8; ++step) {
                    int kw = step * 8 + lk;
                    uint32 b0[2], b1[2];
                    #pragma unroll
                    for (int t = 0; t < 2; ++t) {
                        int n = nq * 16 + t * 8 + lr;
                        b0[t] = __float_as_uint(wt[n * HB_LD + kw]);
                        b1[t] = __float_as_uint(wt[n * HB_LD + kw + 4]);
                    }
                    int kc = ch * 64 + kw;
                    #pragma unroll
                    for (int q = 0; q < 4; ++q) {
                        int r0 = q * 16 + lr;
                        uint32 a0 = cvt_tf32(sm[XS_OFF + r0 * XS_LD + kc]);
                        uint32 a1 = cvt_tf32(sm[XS_OFF + (r0 + 8) * XS_LD + kc]);
                        uint32 a2 = cvt_tf32(sm[XS_OFF + r0 * XS_LD + kc + 4]);
                        uint32 a3 = cvt_tf32(sm[XS_OFF + (r0 + 8) * XS_LD + kc + 4]);
                        #pragma unroll
                        for (int t = 0; t < 2; ++t)
                            mma_tf32(&acc[q * 8 + t * 4], a0, a1, a2, a3, b0[t], b1[t]);
                    }
                }
            }
            __syncthreads();
        }

        // epilogue
        if (wid < 16) {
            const int ms = wid & 3, nq = wid >> 2;
            int rb = ms * 16 + lr;
            #pragma unroll
            for (int t = 0; t < 2; ++t) {
                int cb = nq * 16 + t * 8 + lk * 2;
                float bb0 = __ldg(&bnlin_b[cb]), bb1 = __ldg(&bnlin_b[cb + 1]);
                float2 lo_, hi_;
                lo_.x = tanhf(acc[t * 4 + 0] + bb0); lo_.y = tanhf(acc[t * 4 + 1] + bb1);
                hi_.x = tanhf(acc[t * 4 + 2] + bb0); hi_.y = tanhf(acc[t * 4 + 3] + bb1);
                *reinterpret_cast<float2*>(sm + HH_OFF + rb * HB_LD + cb)       = lo_;
                *reinterpret_cast<float2*>(sm + HH_OFF + (rb + 8) * HB_LD + cb) = hi_;
                float gb0 = __ldg(&gate_b[cb]), gb1 = __ldg(&gate_b[cb + 1]);
                lo_.x = tanhf(acc[8 + t * 4 + 0] + gb0); lo_.y = tanhf(acc[8 + t * 4 + 1] + gb1);
                hi_.x = tanhf(acc[8 + t * 4 + 2] + gb0); hi_.y = tanhf(acc[8 + t * 4 + 3] + gb1);
                *reinterpret_cast<float2*>(sm + MASK_OFF + rb * HB_LD + cb)       = lo_;
                *reinterpret_cast<float2*>(sm + MASK_OFF + (rb + 8) * HB_LD + cb) = hi_;
            }
        } else {
            const int w2 = wid - 16;
            const int matU = w2 >> 2, nq = w2 & 3;
            float* base = sm + (matU ? B_OFF : A_OFF);
            #pragma unroll
            for (int q = 0; q < 4; ++q) {
                int rb = q * 16 + lr;
                #pragma unroll
                for (int t = 0; t < 2; ++t) {
                    int cb = nq * 16 + t * 8 + lk * 2;
                    float2 lo_, hi_;
                    lo_.x = acc[q * 8 + t * 4 + 0]; lo_.y = acc[q * 8 + t * 4 + 1];
                    hi_.x = acc[q * 8 + t * 4 + 2]; hi_.y = acc[q * 8 + t * 4 + 3];
                    *reinterpret_cast<float2*>(base + rb * HB_LD + cb)       = lo_;
                    *reinterpret_cast<float2*>(base + (rb + 8) * HB_LD + cb) = hi_;
                }
            }
        }
    }
    __syncthreads();

    // ---- Stage layer-0 mid weights into WB buf0 (hidden behind ph 2-4) ----
    {
        int mr4 = (MIDREL_F >> 2);
        int mo4 = (MIDROOT_F >> 2);
        for (int g = tid; g < 1024; g += NT) {
            int n = g >> 4, kq = g & 15;
            int dst = n * 17 + kq;
            wb4[dst]        = wT4[mr4 + g];
            wb4[1088 + dst] = wT4[mo4 + g];
        }
    }

    // -------- Phase 2: adjacency logits via Markidis tf32 mma (~2^-22) -----
    if (wid < 16) {
        const int lr = lane >> 2, lk = lane & 3;
        const int ms = wid & 3, nq = wid >> 2;
        const int r0 = ms * 16 + lr;
        const float* xa = sm + HH_OFF;
        float d[2][4];
        #pragma unroll
        for (int t = 0; t < 2; ++t)
            #pragma unroll
            for (int i = 0; i < 4; ++i) d[t][i] = 0.f;
        #pragma unroll
        for (int step = 0; step < 8; ++step) {
            int kc = step * 8 + lk;
            float a0 = xa[r0 * HB_LD + kc];
            float a1 = xa[(r0 + 8) * HB_LD + kc];
            float a2 = xa[r0 * HB_LD + kc + 4];
            float a3 = xa[(r0 + 8) * HB_LD + kc + 4];
            uint32 ah0 = cvt_tf32(a0), ah1 = cvt_tf32(a1), ah2 = cvt_tf32(a2), ah3 = cvt_tf32(a3);
            uint32 al0 = cvt_tf32(a0 - __uint_as_float(ah0));
            uint32 al1 = cvt_tf32(a1 - __uint_as_float(ah1));
            uint32 al2 = cvt_tf32(a2 - __uint_as_float(ah2));
            uint32 al3 = cvt_tf32(a3 - __uint_as_float(ah3));
            #pragma unroll
            for (int t = 0; t < 2; ++t) {
                int n = nq * 16 + t * 8 + lr;
                float b0 = xa[n * HB_LD + kc];
                float b1 = xa[n * HB_LD + kc + 4];
                uint32 bh0 = cvt_tf32(b0), bh1 = cvt_tf32(b1);
                uint32 bl0 = cvt_tf32(b0 - __uint_as_float(bh0));
                uint32 bl1 = cvt_tf32(b1 - __uint_as_float(bh1));
                mma_tf32(d[t], ah0, ah1, ah2, ah3, bh0, bh1);
                mma_tf32(d[t], ah0, ah1, ah2, ah3, bl0, bl1);
                mma_tf32(d[t], al0, al1, al2, al3, bh0, bh1);
            }
        }
        float* adj = sm + ADJ_OFF;
        #pragma unroll
        for (int t = 0; t < 2; ++t) {
            int cb = nq * 16 + t * 8 + lk * 2;
            bool c0ok = cb < CN, c1ok = (cb + 1) < CN;
            if (r0 < CN) {
                if (c0ok) adj[r0 * 64 + cb]     = d[t][0];
                if (c1ok) adj[r0 * 64 + cb + 1] = d[t][1];
            }
            if (r0 + 8 < CN) {
                if (c0ok) adj[(r0 + 8) * 64 + cb]     = d[t][2];
                if (c1ok) adj[(r0 + 8) * 64 + cb + 1] = d[t][3];
            }
        }
    }
    __syncthreads();

    // ---------- Phase 3: softmax + top-10 ----------------------------------
    {
        int* tix = reinterpret_cast<int*>(sm);
        for (int r = wid; r < CN; r += 24) {
            const float* arow = sm + ADJ_OFF + r * 64;
            float a0 = arow[lane];
            bool ok1 = (lane + 32) < CN;
            float a1 = ok1 ? arow[lane + 32] : -1e30f;
            float mx = fmaxf(a0, a1);
            #pragma unroll
            for (int o = 16; o; o >>= 1) mx = fmaxf(mx, __shfl_xor_sync(0xffffffffu, mx, o));
            float e0 = expf(a0 - mx);
            float e1 = ok1 ? expf(a1 - mx) : 0.f;
            float s = e0 + e1;
            #pragma unroll
            for (int o = 16; o; o >>= 1) s += __shfl_xor_sync(0xffffffffu, s, o);
            float inv = 1.f / s;
            float p0 = e0 * inv, p1 = e1 * inv;
            float v0 = p0;
            float v1 = ok1 ? p1 : -1.f;
            for (int m = 0; m < TOPK; ++m) {
                float c  = fmaxf(v0, v1);
                float cm = c;
                #pragma unroll
                for (int o = 16; o; o >>= 1) cm = fmaxf(cm, __shfl_xor_sync(0xffffffffu, cm, o));
                unsigned ball = __ballot_sync(0xffffffffu, c == cm);
                int owner = __ffs(ball) - 1;
                if (lane == owner) {
                    if (v0 == cm) {
                        sm[TV_OFF + r * TOPK + m] = p0;
                        tix[TI_OFF + r * TOPK + m] = lane;
                        v0 = -1.f;
                    } else {
                        sm[TV_OFF + r * TOPK + m] = p1;
                        tix[TI_OFF + r * TOPK + m] = lane + 32;
                        v1 = -1.f;
                    }
                }
            }
        }
    }
    __syncthreads();

    // ---------- Phase 4: h1 = relu(adjS @ A + rel_b1 + B) ------------------
    {
        const int r   = tid >> 3;
        const int cg  = tid & 7;
        const int c0a = cg * 4;
        const int c0b = 32 + cg * 4;
        if (r < CN) {
            const int* tix = reinterpret_cast<const int*>(sm);
            ull s[4] = {0ull, 0ull, 0ull, 0ull};
            #pragma unroll
            for (int m = 0; m < TOPK; ++m) {
                int   j = tix[TI_OFF + r * TOPK + m];
                ull  vp = pack2(sm[TV_OFF + r * TOPK + m]);
                ulonglong2 pa = *reinterpret_cast<const ulonglong2*>(sm + A_OFF + j * HB_LD + c0a);
                ulonglong2 pb = *reinterpret_cast<const ulonglong2*>(sm + A_OFF + j * HB_LD + c0b);
                s[0] = ffma2(vp, pa.x, s[0]);
                s[1] = ffma2(vp, pa.y, s[1]);
                s[2] = ffma2(vp, pb.x, s[2]);
                s[3] = ffma2(vp, pb.y, s[3]);
            }
            float4 r0 = *reinterpret_cast<const float4*>(sm + B_OFF + r * HB_LD + c0a);
            float4 r1 = *reinterpret_cast<const float4*>(sm + B_OFF + r * HB_LD + c0b);
            float2 v0 = unpack2(s[0]), v1 = unpack2(s[1]);
            float2 v2 = unpack2(s[2]), v3 = unpack2(s[3]);
            float4 t0, t1;
            t0.x = fmaxf(v0.x + __ldg(&rel_b1[c0a + 0]) + r0.x, 0.f);
            t0.y = fmaxf(v0.y + __ldg(&rel_b1[c0a + 1]) + r0.y, 0.f);
            t0.z = fmaxf(v1.x + __ldg(&rel_b1[c0a + 2]) + r0.z, 0.f);
            t0.w = fmaxf(v1.y + __ldg(&rel_b1[c0a + 3]) + r0.w, 0.f);
            t1.x = fmaxf(v2.x + __ldg(&rel_b1[c0b + 0]) + r1.x, 0.f);
            t1.y = fmaxf(v2.y + __ldg(&rel_b1[c0b + 1]) + r1.y, 0.f);
            t1.z = fmaxf(v3.x + __ldg(&rel_b1[c0b + 2]) + r1.z, 0.f);
            t1.w = fmaxf(v3.y + __ldg(&rel_b1[c0b + 3]) + r1.w, 0.f);
            *reinterpret_cast<float4*>(sm + HH_OFF + r * HB_LD + c0a) = t0;
            *reinterpret_cast<float4*>(sm + HH_OFF + r * HB_LD + c0b) = t1;
        } else if (r < 64) {
            float4 z = make_float4(0.f, 0.f, 0.f, 0.f);
            *reinterpret_cast<float4*>(sm + HH_OFF + r * HB_LD + c0a) = z;
            *reinterpret_cast<float4*>(sm + HH_OFF + r * HB_LD + c0b) = z;
        }
    }
    __syncthreads();

    // ---------------- Phase 5: six layers (double-buffered staging) --------
    for (int L = 0; L < 6; ++L) {
        // GEMM from buffer L&1: 32 N16-units; warps 0-7 do 2, warps 8-23 do 1
        {
            const int lr = lane >> 2, lk = lane & 3;
            const float* hb = sm + HH_OFF;
            float acc[16];
            #pragma unroll
            for (int i = 0; i < 16; ++i) acc[i] = 0.f;
            const int nunits = (wid < 8) ? 2 : 1;
            for (int sU = 0; sU < nunits; ++sU) {
                int u = sU ? (24 + wid) : wid;
                int mat = u >> 4;
                int within = u & 15;
                int msU = within & 3, nqU = within >> 2;
                const float* wt = sm + WB_OFF + (L & 1) * 8704 + mat * WSLOT;
                int r0 = msU * 16 + lr;
                float* d = acc + sU * 8;
                #pragma unroll
                for (int step = 0; step < 8; ++step) {
                    int kc = step * 8 + lk;
                    uint32 a0 = cvt_tf32(hb[r0 * HB_LD + kc]);
                    uint32 a1 = cvt_tf32(hb[(r0 + 8) * HB_LD + kc]);
                    uint32 a2 = cvt_tf32(hb[r0 * HB_LD + kc + 4]);
                    uint32 a3 = cvt_tf32(hb[(r0 + 8) * HB_LD + kc + 4]);
                    #pragma unroll
                    for (int t = 0; t < 2; ++t) {
                        int n = nqU * 16 + t * 8 + lr;
                        uint32 b0 = __float_as_uint(wt[n * HB_LD + kc]);
                        uint32 b1 = __float_as_uint(wt[n * HB_LD + kc + 4]);
                        mma_tf32(d + t * 4, a0, a1, a2, a3, b0, b1);
                    }
                }
                float* base = sm + (mat ? B_OFF : A_OFF);
                #pragma unroll
                for (int t = 0; t < 2; ++t) {
                    int cb = nqU * 16 + t * 8 + lk * 2;
                    float2 lo_, hi_;
                    lo_.x = d[t * 4 + 0]; lo_.y = d[t * 4 + 1];
                    hi_.x = d[t * 4 + 2]; hi_.y = d[t * 4 + 3];
                    *reinterpret_cast<float2*>(base + r0 * HB_LD + cb)       = lo_;
                    *reinterpret_cast<float2*>(base + (r0 + 8) * HB_LD + cb) = hi_;
                }
            }
        }
        __syncthreads();

        // stage L+1 into the other buffer (overlapped with update)
        if (L < 5) {
            int mr4 = (MIDREL_F >> 2) + (L + 1) * 1024;
            int mo4 = (MIDROOT_F >> 2) + (L + 1) * 1024;
            float4* dstb = wb4 + ((L + 1) & 1) * 2176;
            for (int g = tid; g < 1024; g += NT) {
                int n = g >> 4, kq = g & 15;
                int dst = n * 17 + kq;
                dstb[dst]        = wT4[mr4 + g];
                dstb[1088 + dst] = wT4[mo4 + g];
            }
        }

        // update: t = relu(adjS @ hr + rel_b_mid[L] + hroot); h+=t / out
        {
            const int r   = tid >> 3;
            const int cg  = tid & 7;
            const int c0a = cg * 4;
            const int c0b = 32 + cg * 4;
            if (r < CN) {
                const int* tix = reinterpret_cast<const int*>(sm);
                const float* relb = rel_b_mid + L * 64;
                ull s[4] = {0ull, 0ull, 0ull, 0ull};
                #pragma unroll
                for (int m = 0; m < TOPK; ++m) {
                    int   j = tix[TI_OFF + r * TOPK + m];
                    ull  vp = pack2(sm[TV_OFF + r * TOPK + m]);
                    ulonglong2 pa = *reinterpret_cast<const ulonglong2*>(sm + A_OFF + j * HB_LD + c0a);
                    ulonglong2 pb = *reinterpret_cast<const ulonglong2*>(sm + A_OFF + j * HB_LD + c0b);
                    s[0] = ffma2(vp, pa.x, s[0]);
                    s[1] = ffma2(vp, pa.y, s[1]);
                    s[2] = ffma2(vp, pb.x, s[2]);
                    s[3] = ffma2(vp, pb.y, s[3]);
                }
                float4 r0 = *reinterpret_cast<const float4*>(sm + B_OFF + r * HB_LD + c0a);
                float4 r1 = *reinterpret_cast<const float4*>(sm + B_OFF + r * HB_LD + c0b);
                float2 v0 = unpack2(s[0]), v1 = unpack2(s[1]);
                float2 v2 = unpack2(s[2]), v3 = unpack2(s[3]);
                float4 t0, t1;
                t0.x = fmaxf(v0.x + __ldg(&relb[c0a + 0]) + r0.x, 0.f);
                t0.y = fmaxf(v0.y + __ldg(&relb[c0a + 1]) + r0.y, 0.f);
                t0.z = fmaxf(v1.x + __ldg(&relb[c0a + 2]) + r0.z, 0.f);
                t0.w = fmaxf(v1.y + __ldg(&relb[c0a + 3]) + r0.w, 0.f);
                t1.x = fmaxf(v2.x + __ldg(&relb[c0b + 0]) + r1.x, 0.f);
                t1.y = fmaxf(v2.y + __ldg(&relb[c0b + 1]) + r1.y, 0.f);
                t1.z = fmaxf(v3.x + __ldg(&relb[c0b + 2]) + r1.z, 0.f);
                t1.w = fmaxf(v3.y + __ldg(&relb[c0b + 3]) + r1.w, 0.f);
                float* h0 = sm + HH_OFF + r * HB_LD + c0a;
                float* h1 = sm + HH_OFF + r * HB_LD + c0b;
                if (L < 5) {
                    float4 ha = *reinterpret_cast<const float4*>(h0);
                    float4 hbv = *reinterpret_cast<const float4*>(h1);
                    ha.x += t0.x; ha.y += t0.y; ha.z += t0.z; ha.w += t0.w;
                    hbv.x += t1.x; hbv.y += t1.y; hbv.z += t1.z; hbv.w += t1.w;
                    *reinterpret_cast<float4*>(h0) = ha;
                    *reinterpret_cast<float4*>(h1) = hbv;
                } else {
                    float4 m0 = *reinterpret_cast<const float4*>(sm + MASK_OFF + r * HB_LD + c0a);
                    float4 m1 = *reinterpret_cast<const float4*>(sm + MASK_OFF + r * HB_LD + c0b);
                    float4 o0, o1;
                    o0.x = t0.x * m0.x; o0.y = t0.y * m0.y; o0.z = t0.z * m0.z; o0.w = t0.w * m0.w;
                    o1.x = t1.x * m1.x; o1.y = t1.y * m1.y; o1.z = t1.z * m1.z; o1.w = t1.w * m1.w;
                    float* og = out + (size_t)b * (CN * HID) + r * HID;
                    *reinterpret_cast<float4*>(og + c0a) = o0;
                    *reinterpret_cast<float4*>(og + c0b) = o1;
                }
            }
        }
        if (L < 5) __syncthreads();
    }
}

extern "C" void kernel_launch(void* const* d_in, const int* in_sizes, int n_in,
                              void* d_out, int out_size) {
    const float* x          = (const float*)d_in[0];
    const float* gate_w     = (const float*)d_in[1];
    const float* gate_b     = (const float*)d_in[2];
    const float* bnlin_w    = (const float*)d_in[3];
    const float* bnlin_b    = (const float*)d_in[4];
    const float* rel_w1     = (const float*)d_in[5];
    const float* rel_b1     = (const float*)d_in[6];
    const float* root_w1    = (const float*)d_in[7];
    const float* rel_w_mid  = (const float*)d_in[8];
    const float* rel_b_mid  = (const float*)d_in[9];
    const float* root_w_mid = (const float*)d_in[10];
    float* out = (float*)d_out;

    (void)in_sizes; (void)n_in; (void)out_size;

    prep_weights<<<96, 256>>>(gate_w, bnlin_w, rel_w1, root_w1, rel_w_mid, root_w_mid);

    const int smem_bytes = SMEM_FLOATS * 4;   // 228192
    cudaFuncSetAttribute(residual_graph_kernel,
                         cudaFuncAttributeMaxDynamicSharedMemorySize, smem_bytes);
    residual_graph_kernel<<<NB, NT, smem_bytes>>>(
        x, gate_b, bnlin_b, rel_b1, rel_b_mid, out);
}